// round 14
// baseline (speedup 1.0000x reference)
#include <cuda_runtime.h>
#include <cuda_fp16.h>
#include <cstdint>

#define D_IN  2048
#define H1    128
#define H2    64
#define F1    32
#define BATCH 64
#define TSEQ  512
#define MTOT  (BATCH * TSEQ)   // 32768

typedef unsigned long long ull;

// ---- static device scratch (allocation-free) ----
__device__ float g_xp1[MTOT * H1];                          // 16 MB
__device__ float g_xp1b[BATCH * 128 * H1];                  // 4 MB: chunk-0 K-half-1 partials
__device__ __align__(16) unsigned short g_whi[H1 * D_IN];   // W_ih1 fp16
__device__ int g_flag[BATCH * 4];                           // (bb, chunk) ready flags

// ---------------- packed f32x2 helpers (scan) ----------------
__device__ __forceinline__ void fma2(ull &acc, ull a, ull b) {
    asm("fma.rn.f32x2 %0, %1, %2, %0;" : "+l"(acc) : "l"(a), "l"(b));
}
__device__ __forceinline__ void add2(ull &d, ull a, ull b) {
    asm("add.rn.f32x2 %0, %1, %2;" : "=l"(d) : "l"(a), "l"(b));
}
__device__ __forceinline__ float lo32(ull v) { return __uint_as_float((unsigned)v); }
__device__ __forceinline__ float hi32(ull v) { return __uint_as_float((unsigned)(v >> 32)); }

__device__ __forceinline__ float fast_tanh(float x) {
    float e = __expf(2.0f * x);
    return 1.0f - __fdividef(2.0f, e + 1.0f);
}

#define BAR_SYNC(id, n)   asm volatile("bar.sync %0, %1;"   :: "r"(id), "r"(n) : "memory")
#define BAR_ARRIVE(id, n) asm volatile("bar.arrive %0, %1;" :: "r"(id), "r"(n) : "memory")

__device__ __forceinline__ uint32_t smem_u32(const void* p) {
    uint32_t a;
    asm("{ .reg .u64 t; cvta.to.shared.u64 t, %1; cvt.u32.u64 %0, t; }" : "=r"(a) : "l"(p));
    return a;
}

// acquire-spin on a ready flag
__device__ __forceinline__ void wait_flag(const int* f) {
    unsigned v;
    while (true) {
        asm volatile("ld.acquire.gpu.b32 %0, [%1];" : "=r"(v) : "l"(f) : "memory");
        if (v) break;
        __nanosleep(200);
    }
}

// ---------------- mma.sync / ldmatrix primitives (legal on compute_103) ----------------
__device__ __forceinline__ void mma_f16(float4 &d, uint4 a, uint32_t b0, uint32_t b1) {
    asm volatile(
        "mma.sync.aligned.m16n8k16.row.col.f32.f16.f16.f32 "
        "{%0,%1,%2,%3}, {%4,%5,%6,%7}, {%8,%9}, {%0,%1,%2,%3};"
        : "+f"(d.x), "+f"(d.y), "+f"(d.z), "+f"(d.w)
        : "r"(a.x), "r"(a.y), "r"(a.z), "r"(a.w), "r"(b0), "r"(b1));
}
__device__ __forceinline__ uint4 ldsm4(uint32_t addr) {
    uint4 v;
    asm volatile("ldmatrix.sync.aligned.m8n8.x4.shared.b16 {%0,%1,%2,%3}, [%4];"
        : "=r"(v.x), "=r"(v.y), "=r"(v.z), "=r"(v.w) : "r"(addr));
    return v;
}
__device__ __forceinline__ uint32_t cvt_f16x2(float a, float b) {
    uint32_t r;
    asm("cvt.rn.f16x2.f32 %0, %1, %2;" : "=r"(r) : "f"(b), "f"(a));
    return r;
}

// =====================================================================================
// Kernel 0: convert W_ih1 to fp16; zero ready flags.
// =====================================================================================
__global__ void __launch_bounds__(256, 1) convert_w_kernel(const float* __restrict__ W)
{
    int idx = blockIdx.x * 256 + threadIdx.x;        // 65536 float4s
    if (blockIdx.x == 0) g_flag[threadIdx.x] = 0;    // 256 flags (reset every call)
    float4 v = ((const float4*)W)[idx];
    uint2 hi;
    hi.x = cvt_f16x2(v.x, v.y);
    hi.y = cvt_f16x2(v.z, v.w);
    ((uint2*)g_whi)[idx] = hi;
}

// =====================================================================================
// Parameterized GEMM tile: out[mOut..+128) = X[mIn..+128, kOff..kOff+32*nstg) @ W^T (+bias)
// 256 threads, fp16 1-term, 80B-pitch smem, double-buffered. flagIdx<0 -> no publish.
// =====================================================================================
#define PITCH  80
#define ATILE  (128 * PITCH)       // 10240 B per fp16 tile
#define BUFSZ  (2 * ATILE)         // A, B
#define GSMEM  (512 + 2 * BUFSZ)   // 41472 B

__device__ __forceinline__ void stage_store(char* buf, uint32_t off,
                                            const float4* ra, const uint4* rb)
{
    uint4 a0, a1;
    a0.x = cvt_f16x2(ra[0].x, ra[0].y);
    a0.y = cvt_f16x2(ra[0].z, ra[0].w);
    a0.z = cvt_f16x2(ra[1].x, ra[1].y);
    a0.w = cvt_f16x2(ra[1].z, ra[1].w);
    a1.x = cvt_f16x2(ra[2].x, ra[2].y);
    a1.y = cvt_f16x2(ra[2].z, ra[2].w);
    a1.z = cvt_f16x2(ra[3].x, ra[3].y);
    a1.w = cvt_f16x2(ra[3].z, ra[3].w);
    *(uint4*)(buf + off)              = a0;     // A
    *(uint4*)(buf + off + 16)         = a1;
    *(uint4*)(buf + ATILE + off)      = rb[0];  // B
    *(uint4*)(buf + ATILE + off + 16) = rb[1];
}

__device__ void gemm_tile(const float* __restrict__ X, const float* __restrict__ bias,
                          float* __restrict__ outp,
                          int mIn, int mOut, int kOff, int nstg, int flagIdx)
{
    extern __shared__ __align__(16) char smem[];
    float* biasS = (float*)smem;
    char* bufb = smem + 512;
    const uint32_t sb = smem_u32(bufb);

    const int tid = threadIdx.x, lane = tid & 31, w = tid >> 5;
    const int wm = w & 3, wn = w >> 2;          // 4x2 warp grid, warp tile 32x64

    if (tid < 128) biasS[tid] = bias ? bias[tid] : 0.f;

    const int row = tid >> 1, half = tid & 1;
    const float* Arow = X + (size_t)(mIn + row) * D_IN + kOff + half * 16;
    const char* BG = (const char*)g_whi + ((size_t)row * D_IN + kOff) * 2 + half * 32;
    const uint32_t sts_off = (uint32_t)(row * PITCH + half * 32);

    const uint32_t aoff = (uint32_t)((wm * 32 + (lane & 15)) * PITCH + (lane >> 4) * 16);
    const uint32_t boff = (uint32_t)((wn * 64 + (lane & 7) + ((lane >> 4) & 1) * 8) * PITCH
                                     + ((lane >> 3) & 1) * 16);

    float4 acc[2][8];
#pragma unroll
    for (int mi = 0; mi < 2; ++mi)
#pragma unroll
        for (int ni = 0; ni < 8; ++ni) acc[mi][ni] = make_float4(0.f, 0.f, 0.f, 0.f);

    float4 ra[4];
    uint4 rb[2];
#pragma unroll
    for (int f = 0; f < 4; ++f) ra[f] = *(const float4*)(Arow + f * 4);
    rb[0] = *(const uint4*)(BG);
    rb[1] = *(const uint4*)(BG + 16);
    stage_store(bufb, sts_off, ra, rb);
    __syncthreads();

    for (int i = 0; i < nstg; ++i) {
        const int cur = i & 1;
        if (i + 1 < nstg) {                     // prefetch next stage into regs
            const int ko = (i + 1) * 32;
#pragma unroll
            for (int f = 0; f < 4; ++f) ra[f] = *(const float4*)(Arow + ko + f * 4);
            rb[0] = *(const uint4*)(BG + ko * 2);
            rb[1] = *(const uint4*)(BG + ko * 2 + 16);
        }

        const uint32_t Asm = sb + cur * BUFSZ;
        const uint32_t Bsm = Asm + ATILE;

#pragma unroll
        for (int kc = 0; kc < 2; ++kc) {
            const uint32_t kb = kc * 32;

            uint4 a0 = ldsm4(Asm + aoff + kb);
            uint4 a1 = ldsm4(Asm + aoff + 16 * PITCH + kb);
            uint4 b0 = ldsm4(Bsm + boff + kb);
            uint4 b1 = ldsm4(Bsm + boff + 16 * PITCH + kb);
            uint4 b2 = ldsm4(Bsm + boff + 32 * PITCH + kb);
            uint4 b3 = ldsm4(Bsm + boff + 48 * PITCH + kb);

            mma_f16(acc[0][0], a0, b0.x, b0.y);
            mma_f16(acc[0][1], a0, b0.z, b0.w);
            mma_f16(acc[0][2], a0, b1.x, b1.y);
            mma_f16(acc[0][3], a0, b1.z, b1.w);
            mma_f16(acc[0][4], a0, b2.x, b2.y);
            mma_f16(acc[0][5], a0, b2.z, b2.w);
            mma_f16(acc[0][6], a0, b3.x, b3.y);
            mma_f16(acc[0][7], a0, b3.z, b3.w);
            mma_f16(acc[1][0], a1, b0.x, b0.y);
            mma_f16(acc[1][1], a1, b0.z, b0.w);
            mma_f16(acc[1][2], a1, b1.x, b1.y);
            mma_f16(acc[1][3], a1, b1.z, b1.w);
            mma_f16(acc[1][4], a1, b2.x, b2.y);
            mma_f16(acc[1][5], a1, b2.z, b2.w);
            mma_f16(acc[1][6], a1, b3.x, b3.y);
            mma_f16(acc[1][7], a1, b3.z, b3.w);
        }

        if (i + 1 < nstg) stage_store(bufb + (cur ^ 1) * BUFSZ, sts_off, ra, rb);
        __syncthreads();
    }

    // epilogue: add bias, store fp32
    const int row0 = mOut + wm * 32 + (lane >> 2);
    const int cb = wn * 64 + (lane & 3) * 2;
#pragma unroll
    for (int mi = 0; mi < 2; ++mi)
#pragma unroll
        for (int ni = 0; ni < 8; ++ni) {
            const int r = row0 + mi * 16;
            const int c = cb + ni * 8;
            float2 v;
            v.x = acc[mi][ni].x + biasS[c];
            v.y = acc[mi][ni].y + biasS[c + 1];
            *(float2*)(outp + (size_t)r * H1 + c) = v;
            v.x = acc[mi][ni].z + biasS[c];
            v.y = acc[mi][ni].w + biasS[c + 1];
            *(float2*)(outp + (size_t)(r + 8) * H1 + c) = v;
        }

    if (flagIdx >= 0) {
        __threadfence();
        __syncthreads();
        if (tid == 0)
            asm volatile("st.release.gpu.b32 [%0], %1;"
                         :: "l"(&g_flag[flagIdx]), "r"(1) : "memory");
    }
}

// ---- scan: R6/R11-proven pipelined design; chunk 0 reads xp1 + xp1b halves ----
__device__ void scan_body(
    const float* __restrict__ W_hh1, const float* __restrict__ b_hh1,
    const float* __restrict__ W_ih2, const float* __restrict__ W_hh2,
    const float* __restrict__ b_ih2, const float* __restrict__ b_hh2,
    const float* __restrict__ W_fc1, const float* __restrict__ b_fc1,
    const float* __restrict__ W_fc2, const float* __restrict__ b_fc2,
    float* __restrict__ out)
{
    __shared__ __align__(16) float h1buf[2][H1];
    __shared__ __align__(16) float h2buf[2][H2];

    const int tid = threadIdx.x;
    const int bb = blockIdx.x;

    if (tid < H1) h1buf[1][tid] = 0.f;   // h1(-1), read at t=0
    if (tid < H2) h2buf[1][tid] = 0.f;   // h2(-1)
    __syncthreads();

    if (tid < 128) {
        // ---------------- LAYER 1 ----------------
        const int i = tid;
        ull w1p[64];
#pragma unroll
        for (int k = 0; k < 64; ++k)
            w1p[k] = *(const ull*)(W_hh1 + i * H1 + 2 * k);
        const float bias = b_hh1[i];

        const float* xp  = g_xp1  + (size_t)bb * TSEQ * H1;
        const float* xpb = g_xp1b + (size_t)bb * 128 * H1;
        wait_flag(&g_flag[bb * 4]);      // chunk-0 K-half-1 (partner) ready
        float xv = __ldg(xp + i) + __ldg(xpb + i);

        for (int t = 0; t < TSEQ; ++t) {
            const int s = t & 1;
            BAR_SYNC(3 + s, 256);        // EMPTY[s] (pre-armed by L2 for t=0,1)

            float xnext = 0.f;
            if (t < TSEQ - 1) {
                const int tn = t + 1;
                if ((tn & 127) == 0) wait_flag(&g_flag[bb * 4 + (tn >> 7)]);
                xnext = __ldg(xp + tn * H1 + i);
                if (tn < 128) xnext += __ldg(xpb + tn * H1 + i);
            }

            const ulonglong2* hp = (const ulonglong2*)h1buf[s ^ 1];
            ull a0 = 0, a1 = 0, a2 = 0, a3 = 0;
#pragma unroll
            for (int k = 0; k < 16; ++k) {
                ulonglong2 h01 = hp[2 * k];
                ulonglong2 h23 = hp[2 * k + 1];
                fma2(a0, w1p[4 * k + 0], h01.x);
                fma2(a1, w1p[4 * k + 1], h01.y);
                fma2(a2, w1p[4 * k + 2], h23.x);
                fma2(a3, w1p[4 * k + 3], h23.y);
            }
            ull s01, s23, sall;
            add2(s01, a0, a1);
            add2(s23, a2, a3);
            add2(sall, s01, s23);
            float dot = lo32(sall) + hi32(sall);

            h1buf[s][i] = fast_tanh(xv + bias + dot);
            BAR_ARRIVE(1 + s, 256);      // FULL[s]
            xv = xnext;
        }
    } else {
        // ---------------- LAYER 2 ----------------
        const int u = tid - 128;
        const int j = u >> 1, half = u & 1;

        BAR_ARRIVE(3, 256);              // pre-arm EMPTY[0]
        BAR_ARRIVE(4, 256);              // pre-arm EMPTY[1]

        ull wip[32];
#pragma unroll
        for (int k = 0; k < 32; ++k)
            wip[k] = *(const ull*)(W_ih2 + j * H1 + half * 64 + 2 * k);
        ull whp[16];
#pragma unroll
        for (int k = 0; k < 16; ++k)
            whp[k] = *(const ull*)(W_hh2 + j * H2 + half * 32 + 2 * k);
        const float bias2 = b_ih2[j] + b_hh2[j];

        for (int t = 0; t < TSEQ; ++t) {
            const int s = t & 1;
            BAR_SYNC(1 + s, 256);        // FULL[s]

            ulonglong2 hv[16];
            const ulonglong2* hp = (const ulonglong2*)(h1buf[s] + half * 64);
#pragma unroll
            for (int k = 0; k < 16; ++k) hv[k] = hp[k];
            BAR_ARRIVE(3 + s, 256);      // EMPTY[s]

            ull a0 = 0, a1 = 0, a2 = 0, a3 = 0;
#pragma unroll
            for (int k = 0; k < 8; ++k) {
                fma2(a0, wip[4 * k + 0], hv[2 * k].x);
                fma2(a1, wip[4 * k + 1], hv[2 * k].y);
                fma2(a2, wip[4 * k + 2], hv[2 * k + 1].x);
                fma2(a3, wip[4 * k + 3], hv[2 * k + 1].y);
            }
            const ulonglong2* gp = (const ulonglong2*)(h2buf[s ^ 1] + half * 32);
#pragma unroll
            for (int k = 0; k < 4; ++k) {
                ulonglong2 g01 = gp[2 * k];
                ulonglong2 g23 = gp[2 * k + 1];
                fma2(a0, whp[4 * k + 0], g01.x);
                fma2(a1, whp[4 * k + 1], g01.y);
                fma2(a2, whp[4 * k + 2], g23.x);
                fma2(a3, whp[4 * k + 3], g23.y);
            }
            ull s01, s23, sall;
            add2(s01, a0, a1);
            add2(s23, a2, a3);
            add2(sall, s01, s23);
            float d = lo32(sall) + hi32(sall);

            d += __shfl_xor_sync(0xffffffffu, d, 1);
            if (!half) h2buf[s][j] = fast_tanh(d + bias2);
        }

        BAR_SYNC(6, 128);                // L2-internal: final h2 visible for FC

        if (u < F1) {
            const float* hf = h2buf[(TSEQ - 1) & 1];
            float acc = b_fc1[u];
#pragma unroll
            for (int k = 0; k < H2; ++k) acc = fmaf(W_fc1[u * H2 + k], hf[k], acc);
            float r = fmaxf(acc, 0.f) * W_fc2[u];
#pragma unroll
            for (int sft = 16; sft > 0; sft >>= 1) r += __shfl_xor_sync(0xffffffffu, r, sft);
            if (u == 0) out[bb] = r + b_fc2[0];
        }
    }
}

// =====================================================================================
// Fused kernel, grid 320:
//   blocks 0-63    : scan CTA bb -> first computes chunk-0 K-half-0 itself, then scans
//   blocks 64-127  : chunk-0 K-half-1 (bb = bid-64) into g_xp1b, publishes flag[bb*4]
//   blocks 128-319 : chunks 1-3 full-K tiles, chunk-major
// =====================================================================================
__global__ void __launch_bounds__(256, 1) fused_kernel(
    const float* __restrict__ X, const float* __restrict__ b_ih1,
    const float* __restrict__ W_hh1, const float* __restrict__ b_hh1,
    const float* __restrict__ W_ih2, const float* __restrict__ W_hh2,
    const float* __restrict__ b_ih2, const float* __restrict__ b_hh2,
    const float* __restrict__ W_fc1, const float* __restrict__ b_fc1,
    const float* __restrict__ W_fc2, const float* __restrict__ b_fc2,
    float* __restrict__ out)
{
    const int bid = blockIdx.x;
    if (bid < 64) {
        // own chunk-0 K-half-0 (with bias) into g_xp1, no flag (self-visible)
        gemm_tile(X, b_ih1, g_xp1, bid * TSEQ, bid * TSEQ, 0, 32, -1);
        __syncthreads();
        scan_body(W_hh1, b_hh1, W_ih2, W_hh2, b_ih2, b_hh2,
                  W_fc1, b_fc1, W_fc2, b_fc2, out);
    } else if (bid < 128) {
        const int bb = bid - 64;
        gemm_tile(X, nullptr, g_xp1b, bb * TSEQ, bb * 128, 1024, 32, bb * 4);
    } else {
        const int g = bid - 128;
        const int cc = 1 + (g >> 6), bb = g & 63;
        const int m = bb * TSEQ + cc * 128;
        gemm_tile(X, b_ih1, g_xp1, m, m, 0, 64, bb * 4 + cc);
    }
}

// =====================================================================================
extern "C" void kernel_launch(void* const* d_in, const int* in_sizes, int n_in,
                              void* d_out, int out_size)
{
    const float* x     = (const float*)d_in[0];
    const float* W_ih1 = (const float*)d_in[1];
    const float* W_hh1 = (const float*)d_in[2];
    const float* b_ih1 = (const float*)d_in[3];
    const float* b_hh1 = (const float*)d_in[4];
    const float* W_ih2 = (const float*)d_in[5];
    const float* W_hh2 = (const float*)d_in[6];
    const float* b_ih2 = (const float*)d_in[7];
    const float* b_hh2 = (const float*)d_in[8];
    const float* W_fc1 = (const float*)d_in[9];
    const float* b_fc1 = (const float*)d_in[10];
    const float* W_fc2 = (const float*)d_in[11];
    const float* b_fc2 = (const float*)d_in[12];
    float* out = (float*)d_out;

    convert_w_kernel<<<256, 256>>>(W_ih1);
    cudaFuncSetAttribute(fused_kernel, cudaFuncAttributeMaxDynamicSharedMemorySize, GSMEM);
    fused_kernel<<<320, 256, GSMEM>>>(
        x, b_ih1, W_hh1, b_hh1, W_ih2, W_hh2, b_ih2, b_hh2,
        W_fc1, b_fc1, W_fc2, b_fc2, out);
}

// round 15
// speedup vs baseline: 1.2985x; 1.2985x over previous
#include <cuda_runtime.h>
#include <cuda_fp16.h>
#include <cstdint>

#define D_IN  2048
#define H1    128
#define H2    64
#define F1    32
#define BATCH 64
#define TSEQ  512
#define MTOT  (BATCH * TSEQ)   // 32768

typedef unsigned long long ull;

// ---- static device scratch (allocation-free) ----
__device__ float g_xp1[MTOT * H1];                          // 16 MB
__device__ __align__(16) unsigned short g_whi[H1 * D_IN];   // W_ih1 fp16
__device__ int g_flag[BATCH * 4];                           // (bb, chunk) ready flags

// ---------------- packed f32x2 helpers (scan) ----------------
__device__ __forceinline__ void fma2(ull &acc, ull a, ull b) {
    asm("fma.rn.f32x2 %0, %1, %2, %0;" : "+l"(acc) : "l"(a), "l"(b));
}
__device__ __forceinline__ void add2(ull &d, ull a, ull b) {
    asm("add.rn.f32x2 %0, %1, %2;" : "=l"(d) : "l"(a), "l"(b));
}
__device__ __forceinline__ float lo32(ull v) { return __uint_as_float((unsigned)v); }
__device__ __forceinline__ float hi32(ull v) { return __uint_as_float((unsigned)(v >> 32)); }

__device__ __forceinline__ float fast_tanh(float x) {
    float e = __expf(2.0f * x);
    return 1.0f - __fdividef(2.0f, e + 1.0f);
}

#define BAR_SYNC(id, n)   asm volatile("bar.sync %0, %1;"   :: "r"(id), "r"(n) : "memory")
#define BAR_ARRIVE(id, n) asm volatile("bar.arrive %0, %1;" :: "r"(id), "r"(n) : "memory")

__device__ __forceinline__ uint32_t smem_u32(const void* p) {
    uint32_t a;
    asm("{ .reg .u64 t; cvta.to.shared.u64 t, %1; cvt.u32.u64 %0, t; }" : "=r"(a) : "l"(p));
    return a;
}

// acquire-spin on a ready flag
__device__ __forceinline__ void wait_flag(const int* f) {
    unsigned v;
    while (true) {
        asm volatile("ld.acquire.gpu.b32 %0, [%1];" : "=r"(v) : "l"(f) : "memory");
        if (v) break;
        __nanosleep(200);
    }
}

// ---------------- mma.sync / ldmatrix primitives (legal on compute_103) ----------------
__device__ __forceinline__ void mma_f16(float4 &d, uint4 a, uint32_t b0, uint32_t b1) {
    asm volatile(
        "mma.sync.aligned.m16n8k16.row.col.f32.f16.f16.f32 "
        "{%0,%1,%2,%3}, {%4,%5,%6,%7}, {%8,%9}, {%0,%1,%2,%3};"
        : "+f"(d.x), "+f"(d.y), "+f"(d.z), "+f"(d.w)
        : "r"(a.x), "r"(a.y), "r"(a.z), "r"(a.w), "r"(b0), "r"(b1));
}
__device__ __forceinline__ uint4 ldsm4(uint32_t addr) {
    uint4 v;
    asm volatile("ldmatrix.sync.aligned.m8n8.x4.shared.b16 {%0,%1,%2,%3}, [%4];"
        : "=r"(v.x), "=r"(v.y), "=r"(v.z), "=r"(v.w) : "r"(addr));
    return v;
}
__device__ __forceinline__ uint32_t cvt_f16x2(float a, float b) {
    uint32_t r;
    asm("cvt.rn.f16x2.f32 %0, %1, %2;" : "=r"(r) : "f"(b), "f"(a));
    return r;
}

// =====================================================================================
// Kernel 0: convert W_ih1 to fp16 (single rounding); zero ready flags.
// =====================================================================================
__global__ void __launch_bounds__(256, 1) convert_w_kernel(const float* __restrict__ W)
{
    int idx = blockIdx.x * 256 + threadIdx.x;        // 65536 float4s
    if (blockIdx.x == 0) g_flag[threadIdx.x] = 0;    // 256 flags (reset every call)
    float4 v = ((const float4*)W)[idx];
    uint2 hi;
    hi.x = cvt_f16x2(v.x, v.y);
    hi.y = cvt_f16x2(v.z, v.w);
    ((uint2*)g_whi)[idx] = hi;
}

// =====================================================================================
// Fused kernel: blocks 0-63 = scan (one batch each); blocks 64-319 = GEMM tiles,
// CHUNK-MAJOR (g = bid-64 -> chunk cc = g>>6, batch bb = g&63).
// GEMM is pure fp16 1-term: D = A_f16 * B_f16 (8 MMAs + 4 ldsm per k16 chunk).
// =====================================================================================
#define PITCH  80
#define NSTG   64
#define ATILE  (128 * PITCH)       // 10240 B per fp16 tile
#define BUFSZ  (2 * ATILE)         // A, B
#define GSMEM  (512 + 2 * BUFSZ)   // 41472 B

// 256-thread staging: thread -> (row = tid>>1, half = tid&1): 16 fp32 cols per stage
__device__ __forceinline__ void stage_store(char* buf, uint32_t off,
                                            const float4* ra, const uint4* rb)
{
    uint4 a0, a1;
    a0.x = cvt_f16x2(ra[0].x, ra[0].y);
    a0.y = cvt_f16x2(ra[0].z, ra[0].w);
    a0.z = cvt_f16x2(ra[1].x, ra[1].y);
    a0.w = cvt_f16x2(ra[1].z, ra[1].w);
    a1.x = cvt_f16x2(ra[2].x, ra[2].y);
    a1.y = cvt_f16x2(ra[2].z, ra[2].w);
    a1.z = cvt_f16x2(ra[3].x, ra[3].y);
    a1.w = cvt_f16x2(ra[3].z, ra[3].w);
    *(uint4*)(buf + off)              = a0;     // A
    *(uint4*)(buf + off + 16)         = a1;
    *(uint4*)(buf + ATILE + off)      = rb[0];  // B
    *(uint4*)(buf + ATILE + off + 16) = rb[1];
}

__device__ void gemm_body(int g, const float* __restrict__ X, const float* __restrict__ bias)
{
    extern __shared__ __align__(16) char smem[];
    float* biasS = (float*)smem;
    char* bufb = smem + 512;
    const uint32_t sb = smem_u32(bufb);

    const int tid = threadIdx.x, lane = tid & 31, w = tid >> 5;
    const int wm = w & 3, wn = w >> 2;          // 4x2 warp grid, warp tile 32x64
    const int cc = g >> 6, bb = g & 63;
    const int mBase = bb * TSEQ + cc * 128;

    if (tid < 128) biasS[tid] = bias[tid];

    const int row = tid >> 1, half = tid & 1;
    const float* Arow = X + (size_t)(mBase + row) * D_IN + half * 16;
    const char* BG = (const char*)g_whi + (size_t)row * D_IN * 2 + half * 32;
    const uint32_t sts_off = (uint32_t)(row * PITCH + half * 32);

    const uint32_t aoff = (uint32_t)((wm * 32 + (lane & 15)) * PITCH + (lane >> 4) * 16);
    const uint32_t boff = (uint32_t)((wn * 64 + (lane & 7) + ((lane >> 4) & 1) * 8) * PITCH
                                     + ((lane >> 3) & 1) * 16);

    float4 acc[2][8];
#pragma unroll
    for (int mi = 0; mi < 2; ++mi)
#pragma unroll
        for (int ni = 0; ni < 8; ++ni) acc[mi][ni] = make_float4(0.f, 0.f, 0.f, 0.f);

    float4 ra[4];
    uint4 rb[2];
#pragma unroll
    for (int f = 0; f < 4; ++f) ra[f] = *(const float4*)(Arow + f * 4);
    rb[0] = *(const uint4*)(BG);
    rb[1] = *(const uint4*)(BG + 16);
    stage_store(bufb, sts_off, ra, rb);
    __syncthreads();

    for (int i = 0; i < NSTG; ++i) {
        const int cur = i & 1;
        if (i + 1 < NSTG) {                     // prefetch next stage into regs
            const int ko = (i + 1) * 32;
#pragma unroll
            for (int f = 0; f < 4; ++f) ra[f] = *(const float4*)(Arow + ko + f * 4);
            rb[0] = *(const uint4*)(BG + ko * 2);
            rb[1] = *(const uint4*)(BG + ko * 2 + 16);
        }

        const uint32_t Asm = sb + cur * BUFSZ;
        const uint32_t Bsm = Asm + ATILE;

#pragma unroll
        for (int kc = 0; kc < 2; ++kc) {
            const uint32_t kb = kc * 32;

            uint4 a0 = ldsm4(Asm + aoff + kb);
            uint4 a1 = ldsm4(Asm + aoff + 16 * PITCH + kb);
            uint4 b0 = ldsm4(Bsm + boff + kb);
            uint4 b1 = ldsm4(Bsm + boff + 16 * PITCH + kb);
            uint4 b2 = ldsm4(Bsm + boff + 32 * PITCH + kb);
            uint4 b3 = ldsm4(Bsm + boff + 48 * PITCH + kb);

            mma_f16(acc[0][0], a0, b0.x, b0.y);
            mma_f16(acc[0][1], a0, b0.z, b0.w);
            mma_f16(acc[0][2], a0, b1.x, b1.y);
            mma_f16(acc[0][3], a0, b1.z, b1.w);
            mma_f16(acc[0][4], a0, b2.x, b2.y);
            mma_f16(acc[0][5], a0, b2.z, b2.w);
            mma_f16(acc[0][6], a0, b3.x, b3.y);
            mma_f16(acc[0][7], a0, b3.z, b3.w);
            mma_f16(acc[1][0], a1, b0.x, b0.y);
            mma_f16(acc[1][1], a1, b0.z, b0.w);
            mma_f16(acc[1][2], a1, b1.x, b1.y);
            mma_f16(acc[1][3], a1, b1.z, b1.w);
            mma_f16(acc[1][4], a1, b2.x, b2.y);
            mma_f16(acc[1][5], a1, b2.z, b2.w);
            mma_f16(acc[1][6], a1, b3.x, b3.y);
            mma_f16(acc[1][7], a1, b3.z, b3.w);
        }

        if (i + 1 < NSTG) stage_store(bufb + (cur ^ 1) * BUFSZ, sts_off, ra, rb);
        __syncthreads();
    }

    // epilogue: add bias, store fp32
    const int row0 = mBase + wm * 32 + (lane >> 2);
    const int cb = wn * 64 + (lane & 3) * 2;
#pragma unroll
    for (int mi = 0; mi < 2; ++mi)
#pragma unroll
        for (int ni = 0; ni < 8; ++ni) {
            const int r = row0 + mi * 16;
            const int c = cb + ni * 8;
            float2 v;
            v.x = acc[mi][ni].x + biasS[c];
            v.y = acc[mi][ni].y + biasS[c + 1];
            *(float2*)(g_xp1 + (size_t)r * H1 + c) = v;
            v.x = acc[mi][ni].z + biasS[c];
            v.y = acc[mi][ni].w + biasS[c + 1];
            *(float2*)(g_xp1 + (size_t)(r + 8) * H1 + c) = v;
        }

    // publish: all CTA stores -> per-thread fence -> barrier -> release flag
    __threadfence();
    __syncthreads();
    if (tid == 0)
        asm volatile("st.release.gpu.b32 [%0], %1;"
                     :: "l"(&g_flag[bb * 4 + cc]), "r"(1) : "memory");
}

// ---- scan: R13 pipelined design + depth-8 L1 chains + 2-step xp prefetch ----
__device__ void scan_body(
    const float* __restrict__ W_hh1, const float* __restrict__ b_hh1,
    const float* __restrict__ W_ih2, const float* __restrict__ W_hh2,
    const float* __restrict__ b_ih2, const float* __restrict__ b_hh2,
    const float* __restrict__ W_fc1, const float* __restrict__ b_fc1,
    const float* __restrict__ W_fc2, const float* __restrict__ b_fc2,
    float* __restrict__ out)
{
    __shared__ __align__(16) float h1buf[2][H1];
    __shared__ __align__(16) float h2buf[2][H2];

    const int tid = threadIdx.x;
    const int bb = blockIdx.x;

    if (tid < H1) h1buf[1][tid] = 0.f;   // h1(-1), read at t=0
    if (tid < H2) h2buf[1][tid] = 0.f;   // h2(-1)
    __syncthreads();

    if (tid < 128) {
        // ---------------- LAYER 1 ----------------
        const int i = tid;
        ull w1p[64];
#pragma unroll
        for (int k = 0; k < 64; ++k)
            w1p[k] = *(const ull*)(W_hh1 + i * H1 + 2 * k);
        const float bias = b_hh1[i];

        const float* xp = g_xp1 + (size_t)bb * TSEQ * H1;
        wait_flag(&g_flag[bb * 4]);      // chunk 0 ready
        float xv  = __ldg(xp + i);               // t = 0
        float xn1 = __ldg(xp + H1 + i);          // t = 1 (chunk 0)

        for (int t = 0; t < TSEQ; ++t) {
            const int s = t & 1;
            BAR_SYNC(3 + s, 256);        // EMPTY[s] (pre-armed by L2 for t=0,1)

            // 2-step-ahead prefetch: load xp(t+2); flag wait moves 2 steps early
            float xn2 = 0.f;
            if (t + 2 < TSEQ) {
                const int tn = t + 2;
                if ((tn & 127) == 0) wait_flag(&g_flag[bb * 4 + (tn >> 7)]);
                xn2 = __ldg(xp + tn * H1 + i);
            }

            // depth-8 dot: 8 accumulator chains of 8 fma2 each
            const ulonglong2* hp = (const ulonglong2*)h1buf[s ^ 1];
            ull a0 = 0, a1 = 0, a2 = 0, a3 = 0, a4 = 0, a5 = 0, a6 = 0, a7 = 0;
#pragma unroll
            for (int k = 0; k < 8; ++k) {
                ulonglong2 h01 = hp[4 * k];
                ulonglong2 h23 = hp[4 * k + 1];
                ulonglong2 h45 = hp[4 * k + 2];
                ulonglong2 h67 = hp[4 * k + 3];
                fma2(a0, w1p[8 * k + 0], h01.x);
                fma2(a1, w1p[8 * k + 1], h01.y);
                fma2(a2, w1p[8 * k + 2], h23.x);
                fma2(a3, w1p[8 * k + 3], h23.y);
                fma2(a4, w1p[8 * k + 4], h45.x);
                fma2(a5, w1p[8 * k + 5], h45.y);
                fma2(a6, w1p[8 * k + 6], h67.x);
                fma2(a7, w1p[8 * k + 7], h67.y);
            }
            ull s01, s23, s45, s67, sA, sB, sall;
            add2(s01, a0, a1);
            add2(s23, a2, a3);
            add2(s45, a4, a5);
            add2(s67, a6, a7);
            add2(sA, s01, s23);
            add2(sB, s45, s67);
            add2(sall, sA, sB);
            float dot = lo32(sall) + hi32(sall);

            h1buf[s][i] = fast_tanh(xv + bias + dot);
            BAR_ARRIVE(1 + s, 256);      // FULL[s]
            xv = xn1;
            xn1 = xn2;
        }
    } else {
        // ---------------- LAYER 2 ----------------
        const int u = tid - 128;
        const int j = u >> 1, half = u & 1;

        BAR_ARRIVE(3, 256);              // pre-arm EMPTY[0]
        BAR_ARRIVE(4, 256);              // pre-arm EMPTY[1]

        ull wip[32];
#pragma unroll
        for (int k = 0; k < 32; ++k)
            wip[k] = *(const ull*)(W_ih2 + j * H1 + half * 64 + 2 * k);
        ull whp[16];
#pragma unroll
        for (int k = 0; k < 16; ++k)
            whp[k] = *(const ull*)(W_hh2 + j * H2 + half * 32 + 2 * k);
        const float bias2 = b_ih2[j] + b_hh2[j];

        for (int t = 0; t < TSEQ; ++t) {
            const int s = t & 1;
            BAR_SYNC(1 + s, 256);        // FULL[s]

            ulonglong2 hv[16];
            const ulonglong2* hp = (const ulonglong2*)(h1buf[s] + half * 64);
#pragma unroll
            for (int k = 0; k < 16; ++k) hv[k] = hp[k];
            BAR_ARRIVE(3 + s, 256);      // EMPTY[s]

            ull a0 = 0, a1 = 0, a2 = 0, a3 = 0;
#pragma unroll
            for (int k = 0; k < 8; ++k) {
                fma2(a0, wip[4 * k + 0], hv[2 * k].x);
                fma2(a1, wip[4 * k + 1], hv[2 * k].y);
                fma2(a2, wip[4 * k + 2], hv[2 * k + 1].x);
                fma2(a3, wip[4 * k + 3], hv[2 * k + 1].y);
            }
            const ulonglong2* gp = (const ulonglong2*)(h2buf[s ^ 1] + half * 32);
#pragma unroll
            for (int k = 0; k < 4; ++k) {
                ulonglong2 g01 = gp[2 * k];
                ulonglong2 g23 = gp[2 * k + 1];
                fma2(a0, whp[4 * k + 0], g01.x);
                fma2(a1, whp[4 * k + 1], g01.y);
                fma2(a2, whp[4 * k + 2], g23.x);
                fma2(a3, whp[4 * k + 3], g23.y);
            }
            ull s01, s23, sall;
            add2(s01, a0, a1);
            add2(s23, a2, a3);
            add2(sall, s01, s23);
            float d = lo32(sall) + hi32(sall);

            d += __shfl_xor_sync(0xffffffffu, d, 1);
            if (!half) h2buf[s][j] = fast_tanh(d + bias2);
        }

        BAR_SYNC(6, 128);                // L2-internal: final h2 visible for FC

        if (u < F1) {
            const float* hf = h2buf[(TSEQ - 1) & 1];
            float acc = b_fc1[u];
#pragma unroll
            for (int k = 0; k < H2; ++k) acc = fmaf(W_fc1[u * H2 + k], hf[k], acc);
            float r = fmaxf(acc, 0.f) * W_fc2[u];
#pragma unroll
            for (int sft = 16; sft > 0; sft >>= 1) r += __shfl_xor_sync(0xffffffffu, r, sft);
            if (u == 0) out[bb] = r + b_fc2[0];
        }
    }
}

__global__ void __launch_bounds__(256, 1) fused_kernel(
    const float* __restrict__ X, const float* __restrict__ b_ih1,
    const float* __restrict__ W_hh1, const float* __restrict__ b_hh1,
    const float* __restrict__ W_ih2, const float* __restrict__ W_hh2,
    const float* __restrict__ b_ih2, const float* __restrict__ b_hh2,
    const float* __restrict__ W_fc1, const float* __restrict__ b_fc1,
    const float* __restrict__ W_fc2, const float* __restrict__ b_fc2,
    float* __restrict__ out)
{
    if (blockIdx.x >= 64) {
        gemm_body((int)blockIdx.x - 64, X, b_ih1);
    } else {
        scan_body(W_hh1, b_hh1, W_ih2, W_hh2, b_ih2, b_hh2,
                  W_fc1, b_fc1, W_fc2, b_fc2, out);
    }
}

// =====================================================================================
extern "C" void kernel_launch(void* const* d_in, const int* in_sizes, int n_in,
                              void* d_out, int out_size)
{
    const float* x     = (const float*)d_in[0];
    const float* W_ih1 = (const float*)d_in[1];
    const float* W_hh1 = (const float*)d_in[2];
    const float* b_ih1 = (const float*)d_in[3];
    const float* b_hh1 = (const float*)d_in[4];
    const float* W_ih2 = (const float*)d_in[5];
    const float* W_hh2 = (const float*)d_in[6];
    const float* b_ih2 = (const float*)d_in[7];
    const float* b_hh2 = (const float*)d_in[8];
    const float* W_fc1 = (const float*)d_in[9];
    const float* b_fc1 = (const float*)d_in[10];
    const float* W_fc2 = (const float*)d_in[11];
    const float* b_fc2 = (const float*)d_in[12];
    float* out = (float*)d_out;

    convert_w_kernel<<<256, 256>>>(W_ih1);
    cudaFuncSetAttribute(fused_kernel, cudaFuncAttributeMaxDynamicSharedMemorySize, GSMEM);
    fused_kernel<<<64 + MTOT / 128, 256, GSMEM>>>(
        x, b_ih1, W_hh1, b_hh1, W_ih2, W_hh2, b_ih2, b_hh2,
        W_fc1, b_fc1, W_fc2, b_fc2, out);
}